// round 1
// baseline (speedup 1.0000x reference)
#include <cuda_runtime.h>

// out[b,d] = has_edge[b] ? sum_c w[b,c] * F[i0,d] * F[i1,d]  :  F[b,d]
// D = 128 fixed. targets == arange(B) by construction, so self row == b.
// One warp per target b; lane owns a float4 chunk of the 128-dim row.

#define D_DIM 128
#define WARPS_PER_BLOCK 8

__global__ __launch_bounds__(WARPS_PER_BLOCK * 32)
void tmp_kernel(const float* __restrict__ features,
                const int*   __restrict__ comb_idx,   // [B, C, 2]
                const float* __restrict__ comb_w,     // [B, C]
                const float* __restrict__ has_edge,   // [B]
                float*       __restrict__ out,        // [B, 128]
                int B, int C)
{
    const int warp = threadIdx.x >> 5;
    const int lane = threadIdx.x & 31;
    const int b = blockIdx.x * WARPS_PER_BLOCK + warp;
    if (b >= B) return;

    const float4* __restrict__ f4 = reinterpret_cast<const float4*>(features);
    // row stride in float4 units
    const int RS = D_DIM / 4; // 32

    float4 acc = make_float4(0.f, 0.f, 0.f, 0.f);

    const long base = (long)b * C;
    const int* __restrict__ ci = comb_idx + base * 2;
    const float* __restrict__ cw = comb_w + base;

    for (int c = 0; c < C; ++c) {
        const float w = __ldg(cw + c);
        if (w == 0.0f) break;            // padding is trailing; real weights > 0
        const int i0 = __ldg(ci + 2 * c);
        const int i1 = __ldg(ci + 2 * c + 1);
        const float4 a = __ldg(f4 + (long)i0 * RS + lane);
        const float4 v = __ldg(f4 + (long)i1 * RS + lane);
        acc.x = fmaf(w, a.x * v.x, acc.x);
        acc.y = fmaf(w, a.y * v.y, acc.y);
        acc.z = fmaf(w, a.z * v.z, acc.z);
        acc.w = fmaf(w, a.w * v.w, acc.w);
    }

    if (__ldg(has_edge + b) <= 0.0f) {
        acc = __ldg(f4 + (long)b * RS + lane);   // self feature fallback
    }

    reinterpret_cast<float4*>(out)[(long)b * RS + lane] = acc;
}

extern "C" void kernel_launch(void* const* d_in, const int* in_sizes, int n_in,
                              void* d_out, int out_size)
{
    const float* features = (const float*)d_in[0];
    // d_in[1] = target_nodes (== arange(B)); unused.
    const int*   comb_idx = (const int*)d_in[2];
    const float* comb_w   = (const float*)d_in[3];
    const float* has_edge = (const float*)d_in[4];
    float* out = (float*)d_out;

    const int B = in_sizes[4];            // has_edge element count
    const int C = in_sizes[3] / B;        // comb_w is [B, C]

    const int blocks = (B + WARPS_PER_BLOCK - 1) / WARPS_PER_BLOCK;
    tmp_kernel<<<blocks, WARPS_PER_BLOCK * 32>>>(features, comb_idx, comb_w,
                                                 has_edge, out, B, C);
}

// round 2
// speedup vs baseline: 1.1419x; 1.1419x over previous
#include <cuda_runtime.h>

// out[b,:] = (cnt>0) ? sum_c w[b,c] * F[i0(b,c),:] * F[i1(b,c),:]  :  F[b,:]
// D = 128. One warp per target; lane owns a float4 (4 dims).
// Metadata (weights + index pairs) loaded warp-cooperatively in 32-wide chunks,
// trip count derived by ballot (padding is trailing, real weights > 0),
// combos processed 2 at a time for memory-level parallelism.

#define WARPS_PER_BLOCK 8
#define FULL 0xffffffffu

__global__ __launch_bounds__(WARPS_PER_BLOCK * 32)
void tmp_kernel(const float* __restrict__ features,
                const int2*  __restrict__ comb_idx,   // [B, C] int2 pairs
                const float* __restrict__ comb_w,     // [B, C]
                float*       __restrict__ out,        // [B, 128]
                int B, int C)
{
    const int warp = threadIdx.x >> 5;
    const int lane = threadIdx.x & 31;
    const int b = blockIdx.x * WARPS_PER_BLOCK + warp;
    if (b >= B) return;

    const float4* __restrict__ f4 = reinterpret_cast<const float4*>(features);

    float4 acc = make_float4(0.f, 0.f, 0.f, 0.f);

    const long base = (long)b * C;
    const int2*  __restrict__ ci = comb_idx + base;
    const float* __restrict__ cw = comb_w + base;

    int total = 0;
    for (int c0 = 0; c0 < C; c0 += 32) {
        const int m = c0 + lane;
        float w = 0.0f;
        int2  p = make_int2(0, 0);
        if (m < C) {
            w = __ldg(cw + m);
            p = __ldg(ci + m);
        }
        const unsigned nz = __ballot_sync(FULL, w != 0.0f);
        const int cnt = (nz == FULL) ? 32 : (__ffs(~nz) - 1);

        int j = 0;
        for (; j + 2 <= cnt; j += 2) {
            const int   i00 = __shfl_sync(FULL, p.x, j);
            const int   i01 = __shfl_sync(FULL, p.y, j);
            const float w0  = __shfl_sync(FULL, w,   j);
            const int   i10 = __shfl_sync(FULL, p.x, j + 1);
            const int   i11 = __shfl_sync(FULL, p.y, j + 1);
            const float w1  = __shfl_sync(FULL, w,   j + 1);

            const float4 a0 = __ldg(f4 + (long)i00 * 32 + lane);
            const float4 v0 = __ldg(f4 + (long)i01 * 32 + lane);
            const float4 a1 = __ldg(f4 + (long)i10 * 32 + lane);
            const float4 v1 = __ldg(f4 + (long)i11 * 32 + lane);

            acc.x = fmaf(w0, a0.x * v0.x, acc.x);
            acc.y = fmaf(w0, a0.y * v0.y, acc.y);
            acc.z = fmaf(w0, a0.z * v0.z, acc.z);
            acc.w = fmaf(w0, a0.w * v0.w, acc.w);
            acc.x = fmaf(w1, a1.x * v1.x, acc.x);
            acc.y = fmaf(w1, a1.y * v1.y, acc.y);
            acc.z = fmaf(w1, a1.z * v1.z, acc.z);
            acc.w = fmaf(w1, a1.w * v1.w, acc.w);
        }
        if (j < cnt) {
            const int   i00 = __shfl_sync(FULL, p.x, j);
            const int   i01 = __shfl_sync(FULL, p.y, j);
            const float w0  = __shfl_sync(FULL, w,   j);
            const float4 a0 = __ldg(f4 + (long)i00 * 32 + lane);
            const float4 v0 = __ldg(f4 + (long)i01 * 32 + lane);
            acc.x = fmaf(w0, a0.x * v0.x, acc.x);
            acc.y = fmaf(w0, a0.y * v0.y, acc.y);
            acc.z = fmaf(w0, a0.z * v0.z, acc.z);
            acc.w = fmaf(w0, a0.w * v0.w, acc.w);
        }

        total += cnt;
        if (cnt < 32) break;   // trailing padding reached
    }

    if (total == 0) {
        acc = __ldg(f4 + (long)b * 32 + lane);   // self-feature fallback
    }

    reinterpret_cast<float4*>(out)[(long)b * 32 + lane] = acc;
}

extern "C" void kernel_launch(void* const* d_in, const int* in_sizes, int n_in,
                              void* d_out, int out_size)
{
    const float* features = (const float*)d_in[0];
    // d_in[1] = target_nodes (== arange(B)); unused.
    const int2*  comb_idx = (const int2*)d_in[2];
    const float* comb_w   = (const float*)d_in[3];
    float* out = (float*)d_out;

    const int B = in_sizes[4];            // has_edge element count
    const int C = in_sizes[3] / B;        // comb_w is [B, C]

    const int blocks = (B + WARPS_PER_BLOCK - 1) / WARPS_PER_BLOCK;
    tmp_kernel<<<blocks, WARPS_PER_BLOCK * 32>>>(features, comb_idx, comb_w,
                                                 out, B, C);
}